// round 1
// baseline (speedup 1.0000x reference)
#include <cuda_runtime.h>

#define D_MODEL 1024
#define N_HEADS 16
#define HEAD_DIM 64
#define BATCH 4
#define SEQ 2048
#define M_TOTAL (BATCH * SEQ)  // 8192

// Scratch (allocation-free: __device__ globals)
__device__ float g_Q[(size_t)BATCH * N_HEADS * SEQ * HEAD_DIM];  // [B,H,S,D]
__device__ float g_K[(size_t)BATCH * N_HEADS * SEQ * HEAD_DIM];
__device__ float g_V[(size_t)BATCH * N_HEADS * SEQ * HEAD_DIM];
__device__ float g_O[(size_t)M_TOTAL * D_MODEL];                 // [B*S, D_MODEL]

// ---------------------------------------------------------------------------
// SGEMM NT: C[M,N] = A[M,K] * B[N,K]^T + bias[N]
// BM=BN=128, BK=16, 256 threads, 8x8 outputs/thread.
// scatter=1: write into [B,H,S,D] layout (for Q/K/V projections).
// ---------------------------------------------------------------------------
#define BM 128
#define BN 128
#define BK 16

__global__ void __launch_bounds__(256) sgemm_nt(
    const float* __restrict__ A,
    const float* __restrict__ B,
    const float* __restrict__ bias,
    float* __restrict__ C,
    int M, int N, int K, int scatter)
{
    __shared__ float As[BK][BM];
    __shared__ float Bs[BK][BN];

    const int tid = threadIdx.x;
    const int m0 = blockIdx.y * BM;
    const int n0 = blockIdx.x * BN;

    const int tx = tid & 15;   // 0..15
    const int ty = tid >> 4;   // 0..15

    const int lrow = tid >> 2;        // 0..63
    const int lkv  = (tid & 3) * 4;   // 0,4,8,12

    float acc[8][8];
#pragma unroll
    for (int i = 0; i < 8; i++)
#pragma unroll
        for (int j = 0; j < 8; j++) acc[i][j] = 0.f;

    for (int k0 = 0; k0 < K; k0 += BK) {
#pragma unroll
        for (int p = 0; p < 2; p++) {
            int r = lrow + p * 64;
            float4 a = *(const float4*)&A[(size_t)(m0 + r) * K + k0 + lkv];
            As[lkv + 0][r] = a.x; As[lkv + 1][r] = a.y;
            As[lkv + 2][r] = a.z; As[lkv + 3][r] = a.w;
            float4 b = *(const float4*)&B[(size_t)(n0 + r) * K + k0 + lkv];
            Bs[lkv + 0][r] = b.x; Bs[lkv + 1][r] = b.y;
            Bs[lkv + 2][r] = b.z; Bs[lkv + 3][r] = b.w;
        }
        __syncthreads();

#pragma unroll
        for (int kk = 0; kk < BK; kk++) {
            float4 a0 = *(const float4*)&As[kk][ty * 4];
            float4 a1 = *(const float4*)&As[kk][ty * 4 + 64];
            float4 b0 = *(const float4*)&Bs[kk][tx * 4];
            float4 b1 = *(const float4*)&Bs[kk][tx * 4 + 64];
            float ar[8] = {a0.x, a0.y, a0.z, a0.w, a1.x, a1.y, a1.z, a1.w};
            float br[8] = {b0.x, b0.y, b0.z, b0.w, b1.x, b1.y, b1.z, b1.w};
#pragma unroll
            for (int i = 0; i < 8; i++)
#pragma unroll
                for (int j = 0; j < 8; j++)
                    acc[i][j] += ar[i] * br[j];
        }
        __syncthreads();
    }

    // epilogue
#pragma unroll
    for (int i = 0; i < 8; i++) {
        int r = m0 + ty * 4 + ((i < 4) ? i : (64 + i - 4));
#pragma unroll
        for (int jj = 0; jj < 2; jj++) {
            int c = n0 + tx * 4 + jj * 64;
            float4 v;
            v.x = acc[i][jj * 4 + 0] + bias[c + 0];
            v.y = acc[i][jj * 4 + 1] + bias[c + 1];
            v.z = acc[i][jj * 4 + 2] + bias[c + 2];
            v.w = acc[i][jj * 4 + 3] + bias[c + 3];
            if (!scatter) {
                *(float4*)&C[(size_t)r * N + c] = v;
            } else {
                int b = r >> 11, s = r & 2047;
                int h = c >> 6, d = c & 63;
                size_t idx = (((size_t)(b * N_HEADS + h) * SEQ) + s) * HEAD_DIM + d;
                *(float4*)&C[idx] = v;
            }
        }
    }
}

// ---------------------------------------------------------------------------
// Flash attention, fp32. 1 thread = 1 q row. Block = 128 q rows / 128 threads.
// K/V tiles of 64 rows in shared memory (reads are warp-broadcast).
// grid = (SEQ/128, BATCH*N_HEADS)
// ---------------------------------------------------------------------------
__global__ void __launch_bounds__(128) flash_attn_f32(
    const float* __restrict__ Q,
    const float* __restrict__ K,
    const float* __restrict__ V,
    float* __restrict__ O)
{
    const int r = threadIdx.x;            // q row within block
    const int bh = blockIdx.y;            // batch*head
    const int q0 = blockIdx.x * 128;
    const size_t base = (size_t)bh * SEQ * HEAD_DIM;

    __shared__ float4 sK[64 * 16];
    __shared__ float4 sV[64 * 16];

    float4 q[16];
    const float4* qp = (const float4*)&Q[base + (size_t)(q0 + r) * HEAD_DIM];
#pragma unroll
    for (int d = 0; d < 16; d++) q[d] = qp[d];

    float4 o[16];
#pragma unroll
    for (int d = 0; d < 16; d++) o[d] = make_float4(0.f, 0.f, 0.f, 0.f);

    float mval = -1e30f;
    float l = 0.f;
    const float scale = 0.125f;  // 1/sqrt(64)

    for (int kt = 0; kt < SEQ; kt += 64) {
        const float4* kp = (const float4*)&K[base + (size_t)kt * HEAD_DIM];
        const float4* vp = (const float4*)&V[base + (size_t)kt * HEAD_DIM];
#pragma unroll
        for (int p = 0; p < 8; p++) {
            sK[r + p * 128] = kp[r + p * 128];
            sV[r + p * 128] = vp[r + p * 128];
        }
        __syncthreads();

#pragma unroll 2
        for (int j = 0; j < 64; j++) {
            const float4* kj = &sK[j * 16];
            float s0 = 0.f, s1 = 0.f, s2 = 0.f, s3 = 0.f;
#pragma unroll
            for (int d = 0; d < 16; d++) {
                float4 kk = kj[d];
                s0 += q[d].x * kk.x;
                s1 += q[d].y * kk.y;
                s2 += q[d].z * kk.z;
                s3 += q[d].w * kk.w;
            }
            float s = ((s0 + s1) + (s2 + s3)) * scale;

            const float4* vj = &sV[j * 16];
            if (s <= mval) {
                // common path: running max unchanged, no o rescale
                float p = __expf(s - mval);
                l += p;
#pragma unroll
                for (int d = 0; d < 16; d++) {
                    float4 vv = vj[d];
                    o[d].x += p * vv.x; o[d].y += p * vv.y;
                    o[d].z += p * vv.z; o[d].w += p * vv.w;
                }
            } else {
                // new max: p = exp(0) = 1
                float corr = __expf(mval - s);
                mval = s;
                l = l * corr + 1.f;
#pragma unroll
                for (int d = 0; d < 16; d++) {
                    float4 vv = vj[d];
                    o[d].x = o[d].x * corr + vv.x;
                    o[d].y = o[d].y * corr + vv.y;
                    o[d].z = o[d].z * corr + vv.z;
                    o[d].w = o[d].w * corr + vv.w;
                }
            }
        }
        __syncthreads();
    }

    const float inv = 1.f / l;
    const int b = bh >> 4;
    const int h = bh & 15;
    float4* op = (float4*)&O[((size_t)b * SEQ + (q0 + r)) * D_MODEL + h * HEAD_DIM];
#pragma unroll
    for (int d = 0; d < 16; d++) {
        float4 v = o[d];
        v.x *= inv; v.y *= inv; v.z *= inv; v.w *= inv;
        op[d] = v;
    }
}

// ---------------------------------------------------------------------------
extern "C" void kernel_launch(void* const* d_in, const int* in_sizes, int n_in,
                              void* d_out, int out_size)
{
    const float* query = (const float*)d_in[0];
    const float* key   = (const float*)d_in[1];
    const float* value = (const float*)d_in[2];
    const float* Wq    = (const float*)d_in[3];
    const float* bq    = (const float*)d_in[4];
    const float* Wk    = (const float*)d_in[5];
    const float* bk    = (const float*)d_in[6];
    const float* Wv    = (const float*)d_in[7];
    const float* bv    = (const float*)d_in[8];
    const float* Wo    = (const float*)d_in[9];
    const float* bo    = (const float*)d_in[10];
    float* out = (float*)d_out;

    float *qp, *kp, *vp, *op;
    cudaGetSymbolAddress((void**)&qp, g_Q);
    cudaGetSymbolAddress((void**)&kp, g_K);
    cudaGetSymbolAddress((void**)&vp, g_V);
    cudaGetSymbolAddress((void**)&op, g_O);

    dim3 gemm_grid(D_MODEL / BN, M_TOTAL / BM);  // (8, 64)

    sgemm_nt<<<gemm_grid, 256>>>(query, Wq, bq, qp, M_TOTAL, D_MODEL, D_MODEL, 1);
    sgemm_nt<<<gemm_grid, 256>>>(key,   Wk, bk, kp, M_TOTAL, D_MODEL, D_MODEL, 1);
    sgemm_nt<<<gemm_grid, 256>>>(value, Wv, bv, vp, M_TOTAL, D_MODEL, D_MODEL, 1);

    dim3 attn_grid(SEQ / 128, BATCH * N_HEADS);  // (16, 64)
    flash_attn_f32<<<attn_grid, 128>>>(qp, kp, vp, op);

    sgemm_nt<<<gemm_grid, 256>>>(op, Wo, bo, out, M_TOTAL, D_MODEL, D_MODEL, 0);
}